// round 14
// baseline (speedup 1.0000x reference)
#include <cuda_runtime.h>
#include <cuda_fp16.h>
#include <mma.h>

using namespace nvcuda;

#define N_NODES 50000
#define N_EDGES 800000
#define F_IN    128
#define F_HID   64
#define SCAN_B  1024
#define SCAN_NB ((N_NODES + SCAN_B - 1) / SCAN_B)   // 49

// ---------------- scratch (no allocations allowed) ----------------
__device__ int   g_deg_out_i[N_NODES];   // zeroed at load; re-zeroed by scanC each call
__device__ int   g_deg_in_i [N_NODES];
__device__ float g_norm_out[N_NODES];
__device__ float g_norm_in [N_NODES];
__device__ int   g_off    [N_NODES + 1];
__device__ int   g_bsum   [64];
__device__ int   g_bpre   [64];
__device__ int   g_ticket;               // reset by scanA's last block
__device__ int   g_rank   [N_EDGES];     // edge rank within its dst bucket
__device__ int   g_csr_src[N_EDGES];
__device__ __align__(16) __half g_h[N_NODES * F_HID]; // gemm output, fp16 (128B rows)
__device__ __align__(16) __half g_t[N_NODES * F_HID]; // post-layer1 acts (pre-scaled, fp16)

// ---------------- degree count + per-edge rank capture ----------------
__global__ void count_deg_kernel(const int* __restrict__ src, const int* __restrict__ dst) {
    int e = blockIdx.x * blockDim.x + threadIdx.x;
    if (e < N_EDGES) {
        atomicAdd(&g_deg_out_i[src[e]], 1);
        g_rank[e] = atomicAdd(&g_deg_in_i[dst[e]], 1);
    }
}

// ---------------- scan phase A ----------------
__global__ void __launch_bounds__(SCAN_B) scanA_kernel() {
    __shared__ int warp_sums[32];
    __shared__ int is_last;
    int tid = threadIdx.x;
    int lane = tid & 31, wid = tid >> 5;
    int i = blockIdx.x * SCAN_B + tid;
    int v = (i < N_NODES) ? g_deg_in_i[i] : 0;
    int x = v;
#pragma unroll
    for (int o = 1; o < 32; o <<= 1) {
        int y = __shfl_up_sync(0xffffffffu, x, o);
        if (lane >= o) x += y;
    }
    if (lane == 31) warp_sums[wid] = x;
    __syncthreads();
    if (wid == 0) {
        int s = warp_sums[lane];
#pragma unroll
        for (int o = 1; o < 32; o <<= 1) {
            int y = __shfl_up_sync(0xffffffffu, s, o);
            if (lane >= o) s += y;
        }
        warp_sums[lane] = s;
    }
    __syncthreads();
    int excl = (wid ? warp_sums[wid - 1] : 0) + x - v;
    if (i < N_NODES) g_off[i] = excl;
    if (tid == SCAN_B - 1) {
        g_bsum[blockIdx.x] = excl + v;
        __threadfence();
    }
    __syncthreads();
    if (tid == 0)
        is_last = (atomicAdd(&g_ticket, 1) == (int)gridDim.x - 1);
    __syncthreads();
    if (is_last && wid == 0) {
        __threadfence();
        int acc = 0;
        for (int b = 0; b < SCAN_NB; b += 32) {
            int t = b + lane;
            int bv = (t < SCAN_NB) ? g_bsum[t] : 0;
            int bx = bv;
#pragma unroll
            for (int o = 1; o < 32; o <<= 1) {
                int y = __shfl_up_sync(0xffffffffu, bx, o);
                if (lane >= o) bx += y;
            }
            if (t < SCAN_NB) g_bpre[t] = acc + bx - bv;
            acc += __shfl_sync(0xffffffffu, bx, 31);
        }
        if (lane == 0) g_ticket = 0;
    }
}

// ---------------- scan phase C: finalize offsets + norms; re-zero degrees ----------------
__global__ void __launch_bounds__(SCAN_B) scanC_kernel() {
    int i = blockIdx.x * SCAN_B + threadIdx.x;
    if (i < N_NODES) {
        int off = g_off[i] + g_bpre[blockIdx.x];
        g_off[i] = off;
        g_norm_out[i] = rsqrtf(fmaxf((float)g_deg_out_i[i], 1.f));
        g_norm_in [i] = rsqrtf(fmaxf((float)g_deg_in_i [i], 1.f));
        g_deg_out_i[i] = 0;
        g_deg_in_i [i] = 0;
    }
    if (i == 0) g_off[N_NODES] = N_EDGES;
}

// ---------------- CSR fill: atomic-free, 2 edges/thread ----------------
__global__ void fill_kernel(const int* __restrict__ src, const int* __restrict__ dst) {
    int t = blockIdx.x * blockDim.x + threadIdx.x;
    if (t < N_EDGES / 2) {
        int2 s2 = ((const int2*)src)[t];
        int2 d2 = ((const int2*)dst)[t];
        int2 r2 = ((const int2*)g_rank)[t];
        int p0 = __ldg(&g_off[d2.x]) + r2.x;
        int p1 = __ldg(&g_off[d2.y]) + r2.y;
        g_csr_src[p0] = s2.x;
        g_csr_src[p1] = s2.y;
    }
}

// ---------------- GEMM1 (wmma fp16): g_h = fp16((x * norm_out) @ W1) ----------------
__global__ void __launch_bounds__(128) gemm1_kernel(const float* __restrict__ x,
                                                    const float* __restrict__ W) {
    __shared__ __align__(16) char blob[64 * 136 * 2 + 128 * 72 * 2];  // 35840 B
    __half* xh = (__half*)blob;                    // [64][136]
    __half* wh = (__half*)(blob + 64 * 136 * 2);   // [128][72]
    float*  cs = (float*)blob;                     // [64][64], reused after compute
    int tid = threadIdx.x;
    int wid = tid >> 5;
    int row0 = blockIdx.x * 64;

    for (int i = tid; i < F_IN * F_HID / 4; i += 128) {
        int r = i >> 4, c4 = i & 15;
        float4 v = ((const float4*)W)[i];
        __half* p = &wh[r * 72 + c4 * 4];
        p[0] = __float2half(v.x); p[1] = __float2half(v.y);
        p[2] = __float2half(v.z); p[3] = __float2half(v.w);
    }
    for (int i = tid; i < 64 * 32; i += 128) {
        int r = i >> 5, kq = i & 31;
        int row = row0 + r;
        float4 v = make_float4(0.f, 0.f, 0.f, 0.f);
        float s = 0.f;
        if (row < N_NODES) {
            v = ((const float4*)x)[row * 32 + kq];
            s = g_norm_out[row];
        }
        __half* p = &xh[r * 136 + kq * 4];
        p[0] = __float2half(v.x * s); p[1] = __float2half(v.y * s);
        p[2] = __float2half(v.z * s); p[3] = __float2half(v.w * s);
    }
    __syncthreads();

    wmma::fragment<wmma::accumulator, 16, 16, 16, float> c[4];
#pragma unroll
    for (int n = 0; n < 4; n++) wmma::fill_fragment(c[n], 0.f);
#pragma unroll
    for (int k = 0; k < 8; k++) {
        wmma::fragment<wmma::matrix_a, 16, 16, 16, __half, wmma::row_major> a;
        wmma::load_matrix_sync(a, &xh[wid * 16 * 136 + k * 16], 136);
#pragma unroll
        for (int n = 0; n < 4; n++) {
            wmma::fragment<wmma::matrix_b, 16, 16, 16, __half, wmma::row_major> b;
            wmma::load_matrix_sync(b, &wh[k * 16 * 72 + n * 16], 72);
            wmma::mma_sync(c[n], a, b, c[n]);
        }
    }
    __syncthreads();
#pragma unroll
    for (int n = 0; n < 4; n++)
        wmma::store_matrix_sync(&cs[wid * 16 * 64 + n * 16], c[n], 64, wmma::mem_row_major);
    __syncthreads();
    for (int i = tid; i < 64 * 16; i += 128) {
        int r = i >> 4, c4 = i & 15;
        int row = row0 + r;
        if (row < N_NODES) {
            const float* p = &cs[r * 64 + c4 * 4];
            union { __half2 h[2]; uint2 u; } pk;
            pk.h[0] = __floats2half2_rn(p[0], p[1]);
            pk.h[1] = __floats2half2_rn(p[2], p[3]);
            *reinterpret_cast<uint2*>(&g_h[row * F_HID + c4 * 4]) = pk.u;
        }
    }
}

// ---------------- GEMM2 (wmma fp16): g_h = fp16(g_t @ W2)  (K=64) ----------------
__global__ void __launch_bounds__(128) gemm2_kernel(const float* __restrict__ W) {
    __shared__ __align__(16) char blob[64 * 72 * 2 * 2];   // 18432 B
    __half* xh = (__half*)blob;                  // [64][72]
    __half* wh = (__half*)(blob + 64 * 72 * 2);  // [64][72]
    float*  cs = (float*)blob;                   // [64][64] reused
    int tid = threadIdx.x;
    int wid = tid >> 5;
    int row0 = blockIdx.x * 64;

    for (int i = tid; i < F_HID * F_HID / 4; i += 128) {
        int r = i >> 4, c4 = i & 15;
        float4 v = ((const float4*)W)[i];
        __half* p = &wh[r * 72 + c4 * 4];
        p[0] = __float2half(v.x); p[1] = __float2half(v.y);
        p[2] = __float2half(v.z); p[3] = __float2half(v.w);
    }
    for (int i = tid; i < 64 * 8; i += 128) {
        int r = i >> 3, q = i & 7;
        int row = row0 + r;
        uint4 v = make_uint4(0u, 0u, 0u, 0u);
        if (row < N_NODES) v = ((const uint4*)g_t)[row * 8 + q];
        *reinterpret_cast<uint4*>(&xh[r * 72 + q * 8]) = v;
    }
    __syncthreads();

    wmma::fragment<wmma::accumulator, 16, 16, 16, float> c[4];
#pragma unroll
    for (int n = 0; n < 4; n++) wmma::fill_fragment(c[n], 0.f);
#pragma unroll
    for (int k = 0; k < 4; k++) {
        wmma::fragment<wmma::matrix_a, 16, 16, 16, __half, wmma::row_major> a;
        wmma::load_matrix_sync(a, &xh[wid * 16 * 72 + k * 16], 72);
#pragma unroll
        for (int n = 0; n < 4; n++) {
            wmma::fragment<wmma::matrix_b, 16, 16, 16, __half, wmma::row_major> b;
            wmma::load_matrix_sync(b, &wh[k * 16 * 72 + n * 16], 72);
            wmma::mma_sync(c[n], a, b, c[n]);
        }
    }
    __syncthreads();
#pragma unroll
    for (int n = 0; n < 4; n++)
        wmma::store_matrix_sync(&cs[wid * 16 * 64 + n * 16], c[n], 64, wmma::mem_row_major);
    __syncthreads();
    for (int i = tid; i < 64 * 16; i += 128) {
        int r = i >> 4, c4 = i & 15;
        int row = row0 + r;
        if (row < N_NODES) {
            const float* p = &cs[r * 64 + c4 * 4];
            union { __half2 h[2]; uint2 u; } pk;
            pk.h[0] = __floats2half2_rn(p[0], p[1]);
            pk.h[1] = __floats2half2_rn(p[2], p[3]);
            *reinterpret_cast<uint2*>(&g_h[row * F_HID + c4 * 4]) = pk.u;
        }
    }
}

// ---------------- gather core: 4 nodes/warp, 8 lanes/node, uint4 (8 feats)/lane ------
// sub = lane&7 (feature octet), returns 8 feature sums in two float4.
struct F8 { float4 lo, hi; };
__device__ __forceinline__ F8 gather_sum8(int node, int sub) {
    int valid = (node < N_NODES);
    int beg = valid ? g_off[node] : 0;
    int deg = valid ? (g_off[node + 1] - beg) : 0;
    // max degree over the 4 node-groups in this warp
    int dmax = deg;
    dmax = max(dmax, __shfl_xor_sync(0xffffffffu, dmax, 8));
    dmax = max(dmax, __shfl_xor_sync(0xffffffffu, dmax, 16));
    const uint4* h8 = (const uint4*)g_h;     // 16 B = 8 halves; row = 8 uint4
    float4 l0 = make_float4(0.f, 0.f, 0.f, 0.f), h0 = l0;
    float4 l1 = l0, h1 = l0, l2 = l0, h2 = l0, l3 = l0, h3 = l0;
#define ACC(LI, HI, S)                                              \
    if ((S) >= 0) {                                                 \
        uint4 r = h8[(S) * 8 + sub];                                \
        float2 p0 = __half22float2(*(__half2*)&r.x);                \
        float2 p1 = __half22float2(*(__half2*)&r.y);                \
        float2 p2 = __half22float2(*(__half2*)&r.z);                \
        float2 p3 = __half22float2(*(__half2*)&r.w);                \
        LI.x += p0.x; LI.y += p0.y; LI.z += p1.x; LI.w += p1.y;     \
        HI.x += p2.x; HI.y += p2.y; HI.z += p3.x; HI.w += p3.y;     \
    }
    for (int j = 0; j < dmax; j += 4) {
        int s0 = (j + 0 < deg) ? __ldg(&g_csr_src[beg + j + 0]) : -1;
        int s1 = (j + 1 < deg) ? __ldg(&g_csr_src[beg + j + 1]) : -1;
        int s2 = (j + 2 < deg) ? __ldg(&g_csr_src[beg + j + 2]) : -1;
        int s3 = (j + 3 < deg) ? __ldg(&g_csr_src[beg + j + 3]) : -1;
        ACC(l0, h0, s0)
        ACC(l1, h1, s1)
        ACC(l2, h2, s2)
        ACC(l3, h3, s3)
    }
#undef ACC
    F8 r;
    r.lo.x = l0.x + l1.x + l2.x + l3.x;
    r.lo.y = l0.y + l1.y + l2.y + l3.y;
    r.lo.z = l0.z + l1.z + l2.z + l3.z;
    r.lo.w = l0.w + l1.w + l2.w + l3.w;
    r.hi.x = h0.x + h1.x + h2.x + h3.x;
    r.hi.y = h0.y + h1.y + h2.y + h3.y;
    r.hi.z = h0.z + h1.z + h2.z + h3.z;
    r.hi.w = h0.w + h1.w + h2.w + h3.w;
    return r;
}

// ---------------- gather layer 1: g_t = fp16(relu(sum*norm_in + b1) * norm_out) ------
// 256 threads = 8 warps = 32 nodes/block.
__global__ void __launch_bounds__(256) gather1_kernel(const float* __restrict__ b1) {
    int node = blockIdx.x * 32 + (threadIdx.x >> 3);
    int sub = threadIdx.x & 7;
    F8 a = gather_sum8(node, sub);
    if (node >= N_NODES) return;
    float ni = g_norm_in[node], no = g_norm_out[node];
    float4 bl = ((const float4*)b1)[sub * 2];
    float4 bh = ((const float4*)b1)[sub * 2 + 1];
    float o0 = fmaxf(a.lo.x * ni + bl.x, 0.f) * no;
    float o1 = fmaxf(a.lo.y * ni + bl.y, 0.f) * no;
    float o2 = fmaxf(a.lo.z * ni + bl.z, 0.f) * no;
    float o3 = fmaxf(a.lo.w * ni + bl.w, 0.f) * no;
    float o4 = fmaxf(a.hi.x * ni + bh.x, 0.f) * no;
    float o5 = fmaxf(a.hi.y * ni + bh.y, 0.f) * no;
    float o6 = fmaxf(a.hi.z * ni + bh.z, 0.f) * no;
    float o7 = fmaxf(a.hi.w * ni + bh.w, 0.f) * no;
    union { __half2 h[4]; uint4 u; } pk;
    pk.h[0] = __floats2half2_rn(o0, o1);
    pk.h[1] = __floats2half2_rn(o2, o3);
    pk.h[2] = __floats2half2_rn(o4, o5);
    pk.h[3] = __floats2half2_rn(o6, o7);
    ((uint4*)g_t)[node * 8 + sub] = pk.u;
}

// ---------------- gather layer 2: out = sum*norm_in + b2 (fp32 out) ----------------
__global__ void __launch_bounds__(256) gather2_kernel(const float* __restrict__ b2,
                                                      float* __restrict__ out) {
    int node = blockIdx.x * 32 + (threadIdx.x >> 3);
    int sub = threadIdx.x & 7;
    F8 a = gather_sum8(node, sub);
    if (node >= N_NODES) return;
    float ni = g_norm_in[node];
    float4 bl = ((const float4*)b2)[sub * 2];
    float4 bh = ((const float4*)b2)[sub * 2 + 1];
    float4 ol, oh;
    ol.x = a.lo.x * ni + bl.x; ol.y = a.lo.y * ni + bl.y;
    ol.z = a.lo.z * ni + bl.z; ol.w = a.lo.w * ni + bl.w;
    oh.x = a.hi.x * ni + bh.x; oh.y = a.hi.y * ni + bh.y;
    oh.z = a.hi.z * ni + bh.z; oh.w = a.hi.w * ni + bh.w;
    ((float4*)out)[node * 16 + sub * 2] = ol;
    ((float4*)out)[node * 16 + sub * 2 + 1] = oh;
}

extern "C" void kernel_launch(void* const* d_in, const int* in_sizes, int n_in,
                              void* d_out, int out_size) {
    const float* x   = (const float*)d_in[0];
    const int*   src = (const int*)  d_in[1];
    const int*   dst = (const int*)  d_in[2];
    const float* W1  = (const float*)d_in[3];
    const float* b1  = (const float*)d_in[4];
    const float* W2  = (const float*)d_in[5];
    const float* b2  = (const float*)d_in[6];
    float* out = (float*)d_out;

    const int T = 256;
    const int edgeBlocks   = (N_EDGES + T - 1) / T;        // 3125
    const int fillBlocks   = (N_EDGES / 2 + T - 1) / T;    // 1563
    const int gemmBlocks   = (N_NODES + 63) / 64;          // 782
    const int gatherBlocks = (N_NODES + 31) / 32;          // 1563

    // degrees, norms, CSR
    count_deg_kernel<<<edgeBlocks, T>>>(src, dst);
    scanA_kernel<<<SCAN_NB, SCAN_B>>>();
    scanC_kernel<<<SCAN_NB, SCAN_B>>>();
    fill_kernel<<<fillBlocks, T>>>(src, dst);

    // layer 1
    gemm1_kernel<<<gemmBlocks, 128>>>(x, W1);
    gather1_kernel<<<gatherBlocks, T>>>(b1);

    // layer 2
    gemm2_kernel<<<gemmBlocks, 128>>>(W2);
    gather2_kernel<<<gatherBlocks, T>>>(b2, out);
}

// round 16
// speedup vs baseline: 1.1715x; 1.1715x over previous
#include <cuda_runtime.h>
#include <cuda_fp16.h>
#include <mma.h>

using namespace nvcuda;

#define N_NODES 50000
#define N_EDGES 800000
#define F_IN    128
#define F_HID   64
#define SCAN_B  1024
#define SCAN_NB ((N_NODES + SCAN_B - 1) / SCAN_B)   // 49

// ---------------- scratch (no allocations allowed) ----------------
__device__ int   g_deg_out_i[N_NODES];   // zeroed at load; re-zeroed by scanC each call
__device__ int   g_deg_in_i [N_NODES];
__device__ float g_norm_out[N_NODES];
__device__ float g_norm_in [N_NODES];
__device__ int   g_off    [N_NODES + 1];
__device__ int   g_bsum   [64];
__device__ int   g_bpre   [64];
__device__ int   g_ticket;               // reset by scanA's last block
__device__ int   g_rank   [N_EDGES];     // edge rank within its dst bucket
__device__ int   g_csr_src[N_EDGES];
__device__ __align__(16) __half g_h[N_NODES * F_HID]; // gemm output, fp16 (128B rows)
__device__ __align__(16) __half g_t[N_NODES * F_HID]; // post-layer1 acts (pre-scaled, fp16)

// ---------------- degree count + per-edge rank capture: 2 edges/thread ----------------
__global__ void count_deg_kernel(const int* __restrict__ src, const int* __restrict__ dst) {
    int t = blockIdx.x * blockDim.x + threadIdx.x;
    if (t < N_EDGES / 2) {
        int2 s2 = ((const int2*)src)[t];
        int2 d2 = ((const int2*)dst)[t];
        atomicAdd(&g_deg_out_i[s2.x], 1);
        atomicAdd(&g_deg_out_i[s2.y], 1);
        int r0 = atomicAdd(&g_deg_in_i[d2.x], 1);
        int r1 = atomicAdd(&g_deg_in_i[d2.y], 1);
        ((int2*)g_rank)[t] = make_int2(r0, r1);
    }
}

// ---------------- scan phase A ----------------
__global__ void __launch_bounds__(SCAN_B) scanA_kernel() {
    __shared__ int warp_sums[32];
    __shared__ int is_last;
    int tid = threadIdx.x;
    int lane = tid & 31, wid = tid >> 5;
    int i = blockIdx.x * SCAN_B + tid;
    int v = (i < N_NODES) ? g_deg_in_i[i] : 0;
    int x = v;
#pragma unroll
    for (int o = 1; o < 32; o <<= 1) {
        int y = __shfl_up_sync(0xffffffffu, x, o);
        if (lane >= o) x += y;
    }
    if (lane == 31) warp_sums[wid] = x;
    __syncthreads();
    if (wid == 0) {
        int s = warp_sums[lane];
#pragma unroll
        for (int o = 1; o < 32; o <<= 1) {
            int y = __shfl_up_sync(0xffffffffu, s, o);
            if (lane >= o) s += y;
        }
        warp_sums[lane] = s;
    }
    __syncthreads();
    int excl = (wid ? warp_sums[wid - 1] : 0) + x - v;
    if (i < N_NODES) g_off[i] = excl;
    if (tid == SCAN_B - 1) {
        g_bsum[blockIdx.x] = excl + v;
        __threadfence();
    }
    __syncthreads();
    if (tid == 0)
        is_last = (atomicAdd(&g_ticket, 1) == (int)gridDim.x - 1);
    __syncthreads();
    if (is_last && wid == 0) {
        __threadfence();
        int acc = 0;
        for (int b = 0; b < SCAN_NB; b += 32) {
            int t = b + lane;
            int bv = (t < SCAN_NB) ? g_bsum[t] : 0;
            int bx = bv;
#pragma unroll
            for (int o = 1; o < 32; o <<= 1) {
                int y = __shfl_up_sync(0xffffffffu, bx, o);
                if (lane >= o) bx += y;
            }
            if (t < SCAN_NB) g_bpre[t] = acc + bx - bv;
            acc += __shfl_sync(0xffffffffu, bx, 31);
        }
        if (lane == 0) g_ticket = 0;
    }
}

// ---------------- scan phase C: finalize offsets + norms; re-zero degrees ----------------
__global__ void __launch_bounds__(SCAN_B) scanC_kernel() {
    int i = blockIdx.x * SCAN_B + threadIdx.x;
    if (i < N_NODES) {
        int off = g_off[i] + g_bpre[blockIdx.x];
        g_off[i] = off;
        g_norm_out[i] = rsqrtf(fmaxf((float)g_deg_out_i[i], 1.f));
        g_norm_in [i] = rsqrtf(fmaxf((float)g_deg_in_i [i], 1.f));
        g_deg_out_i[i] = 0;
        g_deg_in_i [i] = 0;
    }
    if (i == 0) g_off[N_NODES] = N_EDGES;
}

// ---------------- CSR fill: atomic-free scalar (measured best) ----------------
__global__ void fill_kernel(const int* __restrict__ src, const int* __restrict__ dst) {
    int e = blockIdx.x * blockDim.x + threadIdx.x;
    if (e < N_EDGES) {
        int pos = __ldg(&g_off[dst[e]]) + g_rank[e];
        g_csr_src[pos] = src[e];
    }
}

// ---------------- GEMM1 (wmma fp16): g_h = fp16((x * norm_out) @ W1) ----------------
__global__ void __launch_bounds__(128) gemm1_kernel(const float* __restrict__ x,
                                                    const float* __restrict__ W) {
    __shared__ __align__(16) char blob[64 * 136 * 2 + 128 * 72 * 2];  // 35840 B
    __half* xh = (__half*)blob;                    // [64][136]
    __half* wh = (__half*)(blob + 64 * 136 * 2);   // [128][72]
    float*  cs = (float*)blob;                     // [64][64], reused after compute
    int tid = threadIdx.x;
    int wid = tid >> 5;
    int row0 = blockIdx.x * 64;

    for (int i = tid; i < F_IN * F_HID / 4; i += 128) {
        int r = i >> 4, c4 = i & 15;
        float4 v = ((const float4*)W)[i];
        __half* p = &wh[r * 72 + c4 * 4];
        p[0] = __float2half(v.x); p[1] = __float2half(v.y);
        p[2] = __float2half(v.z); p[3] = __float2half(v.w);
    }
    for (int i = tid; i < 64 * 32; i += 128) {
        int r = i >> 5, kq = i & 31;
        int row = row0 + r;
        float4 v = make_float4(0.f, 0.f, 0.f, 0.f);
        float s = 0.f;
        if (row < N_NODES) {
            v = ((const float4*)x)[row * 32 + kq];
            s = g_norm_out[row];
        }
        __half* p = &xh[r * 136 + kq * 4];
        p[0] = __float2half(v.x * s); p[1] = __float2half(v.y * s);
        p[2] = __float2half(v.z * s); p[3] = __float2half(v.w * s);
    }
    __syncthreads();

    wmma::fragment<wmma::accumulator, 16, 16, 16, float> c[4];
#pragma unroll
    for (int n = 0; n < 4; n++) wmma::fill_fragment(c[n], 0.f);
#pragma unroll
    for (int k = 0; k < 8; k++) {
        wmma::fragment<wmma::matrix_a, 16, 16, 16, __half, wmma::row_major> a;
        wmma::load_matrix_sync(a, &xh[wid * 16 * 136 + k * 16], 136);
#pragma unroll
        for (int n = 0; n < 4; n++) {
            wmma::fragment<wmma::matrix_b, 16, 16, 16, __half, wmma::row_major> b;
            wmma::load_matrix_sync(b, &wh[k * 16 * 72 + n * 16], 72);
            wmma::mma_sync(c[n], a, b, c[n]);
        }
    }
    __syncthreads();
#pragma unroll
    for (int n = 0; n < 4; n++)
        wmma::store_matrix_sync(&cs[wid * 16 * 64 + n * 16], c[n], 64, wmma::mem_row_major);
    __syncthreads();
    for (int i = tid; i < 64 * 16; i += 128) {
        int r = i >> 4, c4 = i & 15;
        int row = row0 + r;
        if (row < N_NODES) {
            const float* p = &cs[r * 64 + c4 * 4];
            union { __half2 h[2]; uint2 u; } pk;
            pk.h[0] = __floats2half2_rn(p[0], p[1]);
            pk.h[1] = __floats2half2_rn(p[2], p[3]);
            *reinterpret_cast<uint2*>(&g_h[row * F_HID + c4 * 4]) = pk.u;
        }
    }
}

// ---------------- GEMM2 (wmma fp16): g_h = fp16(g_t @ W2)  (K=64) ----------------
__global__ void __launch_bounds__(128) gemm2_kernel(const float* __restrict__ W) {
    __shared__ __align__(16) char blob[64 * 72 * 2 * 2];   // 18432 B
    __half* xh = (__half*)blob;                  // [64][72]
    __half* wh = (__half*)(blob + 64 * 72 * 2);  // [64][72]
    float*  cs = (float*)blob;                   // [64][64] reused
    int tid = threadIdx.x;
    int wid = tid >> 5;
    int row0 = blockIdx.x * 64;

    for (int i = tid; i < F_HID * F_HID / 4; i += 128) {
        int r = i >> 4, c4 = i & 15;
        float4 v = ((const float4*)W)[i];
        __half* p = &wh[r * 72 + c4 * 4];
        p[0] = __float2half(v.x); p[1] = __float2half(v.y);
        p[2] = __float2half(v.z); p[3] = __float2half(v.w);
    }
    for (int i = tid; i < 64 * 8; i += 128) {
        int r = i >> 3, q = i & 7;
        int row = row0 + r;
        uint4 v = make_uint4(0u, 0u, 0u, 0u);
        if (row < N_NODES) v = ((const uint4*)g_t)[row * 8 + q];
        *reinterpret_cast<uint4*>(&xh[r * 72 + q * 8]) = v;
    }
    __syncthreads();

    wmma::fragment<wmma::accumulator, 16, 16, 16, float> c[4];
#pragma unroll
    for (int n = 0; n < 4; n++) wmma::fill_fragment(c[n], 0.f);
#pragma unroll
    for (int k = 0; k < 4; k++) {
        wmma::fragment<wmma::matrix_a, 16, 16, 16, __half, wmma::row_major> a;
        wmma::load_matrix_sync(a, &xh[wid * 16 * 72 + k * 16], 72);
#pragma unroll
        for (int n = 0; n < 4; n++) {
            wmma::fragment<wmma::matrix_b, 16, 16, 16, __half, wmma::row_major> b;
            wmma::load_matrix_sync(b, &wh[k * 16 * 72 + n * 16], 72);
            wmma::mma_sync(c[n], a, b, c[n]);
        }
    }
    __syncthreads();
#pragma unroll
    for (int n = 0; n < 4; n++)
        wmma::store_matrix_sync(&cs[wid * 16 * 64 + n * 16], c[n], 64, wmma::mem_row_major);
    __syncthreads();
    for (int i = tid; i < 64 * 16; i += 128) {
        int r = i >> 4, c4 = i & 15;
        int row = row0 + r;
        if (row < N_NODES) {
            const float* p = &cs[r * 64 + c4 * 4];
            union { __half2 h[2]; uint2 u; } pk;
            pk.h[0] = __floats2half2_rn(p[0], p[1]);
            pk.h[1] = __floats2half2_rn(p[2], p[3]);
            *reinterpret_cast<uint2*>(&g_h[row * F_HID + c4 * 4]) = pk.u;
        }
    }
}

// ---------------- gather core: 2 nodes/warp, 16 lanes/node, half4/lane, 4-edge unroll ----
__device__ __forceinline__ float4 gather_sum16(int node, int sub) {
    int beg = g_off[node];
    int deg = g_off[node + 1] - beg;
    int dmax = max(deg, __shfl_xor_sync(0xffffffffu, deg, 16));
    const uint2* h4 = (const uint2*)g_h;     // 8 B = 4 halves; row = 16 uint2
    float4 a0 = make_float4(0.f, 0.f, 0.f, 0.f);
    float4 a1 = a0, a2 = a0, a3 = a0;
    for (int j = 0; j < dmax; j += 4) {
        int s0 = (j + 0 < deg) ? __ldg(&g_csr_src[beg + j + 0]) : -1;
        int s1 = (j + 1 < deg) ? __ldg(&g_csr_src[beg + j + 1]) : -1;
        int s2 = (j + 2 < deg) ? __ldg(&g_csr_src[beg + j + 2]) : -1;
        int s3 = (j + 3 < deg) ? __ldg(&g_csr_src[beg + j + 3]) : -1;
        if (s0 >= 0) {
            uint2 r = h4[s0 * 16 + sub];
            float2 p = __half22float2(*(__half2*)&r.x);
            float2 q = __half22float2(*(__half2*)&r.y);
            a0.x += p.x; a0.y += p.y; a0.z += q.x; a0.w += q.y;
        }
        if (s1 >= 0) {
            uint2 r = h4[s1 * 16 + sub];
            float2 p = __half22float2(*(__half2*)&r.x);
            float2 q = __half22float2(*(__half2*)&r.y);
            a1.x += p.x; a1.y += p.y; a1.z += q.x; a1.w += q.y;
        }
        if (s2 >= 0) {
            uint2 r = h4[s2 * 16 + sub];
            float2 p = __half22float2(*(__half2*)&r.x);
            float2 q = __half22float2(*(__half2*)&r.y);
            a2.x += p.x; a2.y += p.y; a2.z += q.x; a2.w += q.y;
        }
        if (s3 >= 0) {
            uint2 r = h4[s3 * 16 + sub];
            float2 p = __half22float2(*(__half2*)&r.x);
            float2 q = __half22float2(*(__half2*)&r.y);
            a3.x += p.x; a3.y += p.y; a3.z += q.x; a3.w += q.y;
        }
    }
    a0.x += a1.x + a2.x + a3.x;
    a0.y += a1.y + a2.y + a3.y;
    a0.z += a1.z + a2.z + a3.z;
    a0.w += a1.w + a2.w + a3.w;
    return a0;
}

// ---------------- gather layer 1: g_t = fp16(relu(sum*norm_in + b1) * norm_out) ----------
__global__ void __launch_bounds__(256) gather1_kernel(const float* __restrict__ b1) {
    int node = blockIdx.x * 16 + (threadIdx.x >> 4);
    int sub = threadIdx.x & 15;
    float4 a = gather_sum16(node, sub);
    float ni = g_norm_in[node], no = g_norm_out[node];
    float4 bb = ((const float4*)b1)[sub];
    float ox = fmaxf(a.x * ni + bb.x, 0.f) * no;
    float oy = fmaxf(a.y * ni + bb.y, 0.f) * no;
    float oz = fmaxf(a.z * ni + bb.z, 0.f) * no;
    float ow = fmaxf(a.w * ni + bb.w, 0.f) * no;
    union { __half2 h[2]; uint2 u; } pk;
    pk.h[0] = __floats2half2_rn(ox, oy);
    pk.h[1] = __floats2half2_rn(oz, ow);
    ((uint2*)g_t)[node * 16 + sub] = pk.u;
}

// ---------------- gather layer 2: out = sum*norm_in + b2 (fp32 out) ----------------
__global__ void __launch_bounds__(256) gather2_kernel(const float* __restrict__ b2,
                                                      float* __restrict__ out) {
    int node = blockIdx.x * 16 + (threadIdx.x >> 4);
    int sub = threadIdx.x & 15;
    float4 a = gather_sum16(node, sub);
    float ni = g_norm_in[node];
    float4 bb = ((const float4*)b2)[sub];
    float4 o;
    o.x = a.x * ni + bb.x;
    o.y = a.y * ni + bb.y;
    o.z = a.z * ni + bb.z;
    o.w = a.w * ni + bb.w;
    ((float4*)out)[node * 16 + sub] = o;
}

extern "C" void kernel_launch(void* const* d_in, const int* in_sizes, int n_in,
                              void* d_out, int out_size) {
    const float* x   = (const float*)d_in[0];
    const int*   src = (const int*)  d_in[1];
    const int*   dst = (const int*)  d_in[2];
    const float* W1  = (const float*)d_in[3];
    const float* b1  = (const float*)d_in[4];
    const float* W2  = (const float*)d_in[5];
    const float* b2  = (const float*)d_in[6];
    float* out = (float*)d_out;

    const int T = 256;
    const int edgeBlocks   = (N_EDGES + T - 1) / T;        // 3125
    const int cntBlocks    = (N_EDGES / 2 + T - 1) / T;    // 1563
    const int gemmBlocks   = (N_NODES + 63) / 64;          // 782
    const int gatherBlocks = N_NODES / 16;                 // 3125 exact

    // degrees, norms, CSR
    count_deg_kernel<<<cntBlocks, T>>>(src, dst);
    scanA_kernel<<<SCAN_NB, SCAN_B>>>();
    scanC_kernel<<<SCAN_NB, SCAN_B>>>();
    fill_kernel<<<edgeBlocks, T>>>(src, dst);

    // layer 1
    gemm1_kernel<<<gemmBlocks, 128>>>(x, W1);
    gather1_kernel<<<gatherBlocks, T>>>(b1);

    // layer 2
    gemm2_kernel<<<gemmBlocks, 128>>>(W2);
    gather2_kernel<<<gatherBlocks, T>>>(b2, out);
}